// round 4
// baseline (speedup 1.0000x reference)
#include <cuda_runtime.h>
#include <cuda_fp16.h>
#include <cstdint>
#include <cstddef>

#define DINLINE __device__ __forceinline__

// ---------------- problem constants ----------------
#define B_ROWS   65536
#define FEAT     1024
#define OUTW     2048

// ---------------- tiling ----------------
#define MT       128
#define NT       128
#define KC       64          // k elements per stage (fp16 -> 128B rows, SW128)
#define KITERS   16          // FEAT / KC
#define NTHREADS 256

// smem per stage: A_hi | A_lo | B_hi | B_lo, each 128 rows x 128B = 16KB
#define AB       16384
#define BB       16384
#define STAGE    (2*AB + 2*BB)       // 64 KB
#define SMEM_TOTAL (2*STAGE)         // 128 KB

#define SWZ(x) ((x) ^ (((x) >> 3) & 0x70))

// scratch: W transposed to [n][k] (K contiguous) and fp16 hi/lo split
__device__ __align__(16) __half g_Wt_hi[FEAT * FEAT];
__device__ __align__(16) __half g_Wt_lo[FEAT * FEAT];

// ---------------- helpers ----------------
DINLINE uint32_t smem_u32(const void* p) {
    uint32_t a;
    asm("{ .reg .u64 t; cvta.to.shared.u64 t, %1; cvt.u32.u64 %0, t; }" : "=r"(a) : "l"(p));
    return a;
}
DINLINE uint32_t pkh(__half a, __half b) {
    __half2 t = __halves2half2(a, b);
    return *reinterpret_cast<uint32_t*>(&t);
}

#define LDSM4(r0, r1, r2, r3, a) \
    asm volatile("ldmatrix.sync.aligned.m8n8.x4.shared.b16 {%0,%1,%2,%3}, [%4];" \
                 : "=r"(r0), "=r"(r1), "=r"(r2), "=r"(r3) : "r"(a))

#define MMA16816(d, a, b) \
    asm volatile("mma.sync.aligned.m16n8k16.row.col.f32.f16.f16.f32 " \
                 "{%0,%1,%2,%3},{%4,%5,%6,%7},{%8,%9},{%0,%1,%2,%3};" \
                 : "+f"((d)[0]), "+f"((d)[1]), "+f"((d)[2]), "+f"((d)[3]) \
                 : "r"((a)[0]), "r"((a)[1]), "r"((a)[2]), "r"((a)[3]), \
                   "r"((b)[0]), "r"((b)[1]))

#define CP16(s, g)  asm volatile("cp.async.cg.shared.global [%0], [%1], 16;" :: "r"(s), "l"(g))
#define CPCOMMIT()  asm volatile("cp.async.commit_group;" ::: "memory")
#define CPWAIT0()   asm volatile("cp.async.wait_group 0;" ::: "memory")

DINLINE float t2v_periodic(float z, float s_w, float c_w) {
    // range-reduce then fast sin/cos
    float n = rintf(z * 0.15915494309189535f);
    float t = fmaf(n, -6.2831854820251465f, z);
    t = fmaf(n, 1.7484556000744487e-7f, t);
    return fmaf(s_w, __sinf(t), c_w * __cosf(t));
}

// ---------------- prologue: transpose + fp16-split W ----------------
__global__ void t2v_cvtW(const float* __restrict__ W) {
    __shared__ float tile[32][33];
    int n = blockIdx.x * 32 + threadIdx.x;
    int k = blockIdx.y * 32 + threadIdx.y;
    tile[threadIdx.y][threadIdx.x] = W[(size_t)k * FEAT + n];
    __syncthreads();
    int nOut = blockIdx.x * 32 + threadIdx.y;
    int kOut = blockIdx.y * 32 + threadIdx.x;
    float v = tile[threadIdx.x][threadIdx.y];
    __half h = __float2half_rn(v);
    float r = v - __half2float(h);
    size_t o = (size_t)nOut * FEAT + kOut;
    g_Wt_hi[o] = h;
    g_Wt_lo[o] = __float2half_rn(r);
}

// ---------------- main fused GEMM + Time2Vec ----------------
__global__ __launch_bounds__(NTHREADS, 1)
void t2v_gemm(const float* __restrict__ x,
              const float* __restrict__ P,
              const float* __restrict__ wq,
              const float* __restrict__ pq,
              const float* __restrict__ swq,
              const float* __restrict__ cwq,
              float* __restrict__ out) {
    extern __shared__ char smem[];
    const uint32_t sb = smem_u32(smem);
    const int tid = threadIdx.x;
    const int wid = tid >> 5;
    const int l   = tid & 31;
    const int wm  = wid >> 1;          // 0..3  (M direction, 32 rows each)
    const int wn  = wid & 1;           // 0..1  (N direction, 64 cols each)

    const int nT = blockIdx.x;         // N fastest -> A rows shared in L2
    const int mT = blockIdx.y;
    const int m0 = mT * MT;
    const int n0 = nT * NT;

    const float wv = wq[0], pv = pq[0];
    const bool worig = (nT == 0);

    // ldmatrix per-lane address components (SW128: xor term = (row&7)<<4)
    const uint32_t aBase = (uint32_t)(wm * 32 + (l & 15)) * 128;
    const uint32_t kA    = (uint32_t)(l >> 4) * 16;
    const uint32_t bBase = (uint32_t)(wn * 64 + ((l >> 4) << 3) + (l & 7)) * 128;
    const uint32_t kB    = (uint32_t)((l >> 3) & 1) * 16;
    const uint32_t lx    = (uint32_t)(l & 7) << 4;

    float acc[2][8][4];
#pragma unroll
    for (int a = 0; a < 2; ++a)
#pragma unroll
        for (int b = 0; b < 8; ++b)
#pragma unroll
            for (int c = 0; c < 4; ++c) acc[a][b][c] = 0.f;

    float4 aR[8];

#define LOAD_A(kc) do { const int kb = (kc) * KC; \
    _Pragma("unroll") \
    for (int i = 0; i < 8; ++i) \
        aR[i] = *(const float4*)(x + (size_t)(m0 + i * 16 + (tid >> 4)) * FEAT + kb + (tid & 15) * 4); \
    } while (0)

#define STS_A(kc, st) do { const int kb = (kc) * KC; \
    _Pragma("unroll") \
    for (int i = 0; i < 8; ++i) { \
        const int row = i * 16 + (tid >> 4); const int c4 = tid & 15; \
        const float4 v = aR[i]; \
        if (worig) { \
            float4 o; \
            o.x = fmaf(wv, v.x, pv); o.y = fmaf(wv, v.y, pv); \
            o.z = fmaf(wv, v.z, pv); o.w = fmaf(wv, v.w, pv); \
            *(float4*)(out + (size_t)(m0 + row) * OUTW + kb + c4 * 4) = o; \
        } \
        __half h0 = __float2half_rn(v.x), h1 = __float2half_rn(v.y); \
        __half h2 = __float2half_rn(v.z), h3 = __float2half_rn(v.w); \
        __half e0 = __float2half_rn(v.x - __half2float(h0)); \
        __half e1 = __float2half_rn(v.y - __half2float(h1)); \
        __half e2 = __float2half_rn(v.z - __half2float(h2)); \
        __half e3 = __float2half_rn(v.w - __half2float(h3)); \
        const uint32_t off = SWZ((uint32_t)(row * 128 + c4 * 8)); \
        *(uint2*)(smem + (st) + off)      = make_uint2(pkh(h0, h1), pkh(h2, h3)); \
        *(uint2*)(smem + (st) + AB + off) = make_uint2(pkh(e0, e1), pkh(e2, e3)); \
    } } while (0)

#define CPB(kc, st) do { const int kb = (kc) * KC; \
    _Pragma("unroll") \
    for (int i = 0; i < 4; ++i) { \
        const int row = i * 32 + (tid >> 3); const int ch = tid & 7; \
        const size_t g = (size_t)(n0 + row) * FEAT + kb + ch * 8; \
        const uint32_t so = sb + (st) + 2 * AB + SWZ((uint32_t)(row * 128 + ch * 16)); \
        CP16(so, g_Wt_hi + g); \
        CP16(so + BB, g_Wt_lo + g); \
    } } while (0)

#define COMPUTE(st) do { \
    _Pragma("unroll") \
    for (int ks = 0; ks < 4; ++ks) { \
        uint32_t ah[2][4], ae[2][4], bh[8][2], be[8][2]; \
        const uint32_t ka  = ((uint32_t)(ks * 32) + kA) ^ lx; \
        const uint32_t kbb = ((uint32_t)(ks * 32) + kB) ^ lx; \
        _Pragma("unroll") \
        for (int mt = 0; mt < 2; ++mt) { \
            const uint32_t ad = sb + (st) + aBase + mt * 2048 + ka; \
            LDSM4(ah[mt][0], ah[mt][1], ah[mt][2], ah[mt][3], ad); \
            LDSM4(ae[mt][0], ae[mt][1], ae[mt][2], ae[mt][3], ad + AB); \
        } \
        _Pragma("unroll") \
        for (int g4 = 0; g4 < 4; ++g4) { \
            const uint32_t bd = sb + (st) + 2 * AB + bBase + g4 * 2048 + kbb; \
            LDSM4(bh[2*g4][0], bh[2*g4][1], bh[2*g4+1][0], bh[2*g4+1][1], bd); \
            LDSM4(be[2*g4][0], be[2*g4][1], be[2*g4+1][0], be[2*g4+1][1], bd + BB); \
        } \
        _Pragma("unroll") \
        for (int mt = 0; mt < 2; ++mt) \
            _Pragma("unroll") \
            for (int nn = 0; nn < 8; ++nn) { \
                MMA16816(acc[mt][nn], ah[mt], bh[nn]); \
                MMA16816(acc[mt][nn], ah[mt], be[nn]); \
                MMA16816(acc[mt][nn], ae[mt], bh[nn]); \
            } \
    } } while (0)

    // ---- prologue: fill stage 0 ----
    LOAD_A(0);
    CPB(0, 0u);
    CPCOMMIT();
    STS_A(0, 0u);
    CPWAIT0();
    __syncthreads();

    // ---- 2-stage pipelined mainloop ----
    for (int kc = 0; kc < KITERS; ++kc) {
        const uint32_t st  = (uint32_t)(kc & 1) * STAGE;
        const uint32_t stn = STAGE - st;
        if (kc + 1 < KITERS) {
            LOAD_A(kc + 1);          // LDG latency hidden behind COMPUTE
            CPB(kc + 1, stn);
            CPCOMMIT();
        }
        COMPUTE(st);
        if (kc + 1 < KITERS) {
            STS_A(kc + 1, stn);
            CPWAIT0();
        }
        __syncthreads();
    }

    // ---- epilogue: z + P -> sine_w*sin + cosine_w*cos ----
    const float s_w = swq[0], c_w = cwq[0];
#pragma unroll
    for (int mt = 0; mt < 2; ++mt) {
        const int r0 = m0 + wm * 32 + mt * 16 + (l >> 2);
#pragma unroll
        for (int nn = 0; nn < 8; ++nn) {
            const int c = n0 + wn * 64 + nn * 8 + (l & 3) * 2;
            const float p0 = __ldg(P + c);
            const float p1 = __ldg(P + c + 1);
            float2 o0, o1;
            o0.x = t2v_periodic(acc[mt][nn][0] + p0, s_w, c_w);
            o0.y = t2v_periodic(acc[mt][nn][1] + p1, s_w, c_w);
            o1.x = t2v_periodic(acc[mt][nn][2] + p0, s_w, c_w);
            o1.y = t2v_periodic(acc[mt][nn][3] + p1, s_w, c_w);
            *(float2*)(out + (size_t)r0 * OUTW + FEAT + c) = o0;
            *(float2*)(out + (size_t)(r0 + 8) * OUTW + FEAT + c) = o1;
        }
    }
}

// ---------------- launch ----------------
extern "C" void kernel_launch(void* const* d_in, const int* in_sizes, int n_in,
                              void* d_out, int out_size) {
    (void)in_sizes; (void)n_in; (void)out_size;
    const float* x  = (const float*)d_in[0];
    const float* W  = (const float*)d_in[1];
    const float* P  = (const float*)d_in[2];
    const float* w  = (const float*)d_in[3];
    const float* p  = (const float*)d_in[4];
    const float* sw = (const float*)d_in[5];
    const float* cw = (const float*)d_in[6];
    float* out = (float*)d_out;

    cudaFuncSetAttribute(t2v_gemm, cudaFuncAttributeMaxDynamicSharedMemorySize, SMEM_TOTAL);

    t2v_cvtW<<<dim3(FEAT / 32, FEAT / 32), dim3(32, 32)>>>(W);
    t2v_gemm<<<dim3(FEAT / NT, B_ROWS / MT), NTHREADS, SMEM_TOTAL>>>(x, P, w, p, sw, cw, out);
}

// round 5
// speedup vs baseline: 1.0032x; 1.0032x over previous
#include <cuda_runtime.h>
#include <cuda_fp16.h>
#include <cstdint>
#include <cstddef>

#define DINLINE __device__ __forceinline__

// ---------------- problem constants ----------------
#define B_ROWS   65536
#define FEAT     1024
#define OUTW     2048

// ---------------- tiling ----------------
#define MT       128
#define NT       128
#define KC       64          // k elements per stage (fp16 -> 128B rows, SW128)
#define KITERS   16          // FEAT / KC
#define NTHREADS 256
#define NSTAGES  3

// one plane (hi or lo) of a 128x64 fp16 tile: 128 rows x 128B = 16KB
#define AB       16384
#define BB       16384
#define STAGE    (2*AB + 2*BB)           // 64 KB
#define SMEM_TOTAL (NSTAGES * STAGE)     // 192 KB

#define SWZ(x) ((x) ^ (((x) >> 3) & 0x70))

// scratch: pre-split operands (fp16 hi/lo planes), W transposed to [n][k]
__device__ __align__(16) __half g_Wt_hi[FEAT * FEAT];
__device__ __align__(16) __half g_Wt_lo[FEAT * FEAT];
__device__ __align__(16) __half g_x_hi[(size_t)B_ROWS * FEAT];
__device__ __align__(16) __half g_x_lo[(size_t)B_ROWS * FEAT];

// ---------------- helpers ----------------
DINLINE uint32_t smem_u32(const void* p) {
    uint32_t a;
    asm("{ .reg .u64 t; cvta.to.shared.u64 t, %1; cvt.u32.u64 %0, t; }" : "=r"(a) : "l"(p));
    return a;
}
DINLINE uint32_t pkh(__half a, __half b) {
    __half2 t = __halves2half2(a, b);
    return *reinterpret_cast<uint32_t*>(&t);
}

#define LDSM4(r0, r1, r2, r3, a) \
    asm volatile("ldmatrix.sync.aligned.m8n8.x4.shared.b16 {%0,%1,%2,%3}, [%4];" \
                 : "=r"(r0), "=r"(r1), "=r"(r2), "=r"(r3) : "r"(a))

#define MMA16816(d, a, b) \
    asm volatile("mma.sync.aligned.m16n8k16.row.col.f32.f16.f16.f32 " \
                 "{%0,%1,%2,%3},{%4,%5,%6,%7},{%8,%9},{%0,%1,%2,%3};" \
                 : "+f"((d)[0]), "+f"((d)[1]), "+f"((d)[2]), "+f"((d)[3]) \
                 : "r"((a)[0]), "r"((a)[1]), "r"((a)[2]), "r"((a)[3]), \
                   "r"((b)[0]), "r"((b)[1]))

#define CP16(s, g)  asm volatile("cp.async.cg.shared.global [%0], [%1], 16;" :: "r"(s), "l"(g))
#define CPCOMMIT()  asm volatile("cp.async.commit_group;" ::: "memory")
#define CPWAIT1()   asm volatile("cp.async.wait_group 1;" ::: "memory")

DINLINE float t2v_periodic(float z, float s_w, float c_w) {
    float n = rintf(z * 0.15915494309189535f);
    float t = fmaf(n, -6.2831854820251465f, z);
    t = fmaf(n, 1.7484556000744487e-7f, t);
    return fmaf(s_w, __sinf(t), c_w * __cosf(t));
}

// ---------------- prologue 1: transpose + fp16-split W ----------------
__global__ void t2v_cvtW(const float* __restrict__ W) {
    __shared__ float tile[32][33];
    int n = blockIdx.x * 32 + threadIdx.x;
    int k = blockIdx.y * 32 + threadIdx.y;
    tile[threadIdx.y][threadIdx.x] = W[(size_t)k * FEAT + n];
    __syncthreads();
    int nOut = blockIdx.x * 32 + threadIdx.y;
    int kOut = blockIdx.y * 32 + threadIdx.x;
    float v = tile[threadIdx.x][threadIdx.y];
    __half h = __float2half_rn(v);
    float r = v - __half2float(h);
    size_t o = (size_t)nOut * FEAT + kOut;
    g_Wt_hi[o] = h;
    g_Wt_lo[o] = __float2half_rn(r);
}

// ---------------- prologue 2: split x + emit original half ----------------
__global__ __launch_bounds__(256, 8)
void t2v_cvtX(const float* __restrict__ x,
              const float* __restrict__ wq,
              const float* __restrict__ pq,
              float* __restrict__ out) {
    const size_t idx = (size_t)blockIdx.x * 256 + threadIdx.x;  // one float4 each
    const float wv = wq[0], pv = pq[0];
    const size_t row = idx >> 8;          // FEAT/4 = 256 float4 per row
    const size_t c4  = idx & 255;
    const float4 v = *(const float4*)(x + row * FEAT + c4 * 4);

    float4 o;
    o.x = fmaf(wv, v.x, pv);
    o.y = fmaf(wv, v.y, pv);
    o.z = fmaf(wv, v.z, pv);
    o.w = fmaf(wv, v.w, pv);
    *(float4*)(out + row * OUTW + c4 * 4) = o;

    __half h0 = __float2half_rn(v.x), h1 = __float2half_rn(v.y);
    __half h2 = __float2half_rn(v.z), h3 = __float2half_rn(v.w);
    __half e0 = __float2half_rn(v.x - __half2float(h0));
    __half e1 = __float2half_rn(v.y - __half2float(h1));
    __half e2 = __float2half_rn(v.z - __half2float(h2));
    __half e3 = __float2half_rn(v.w - __half2float(h3));
    *(uint2*)(g_x_hi + row * FEAT + c4 * 4) = make_uint2(pkh(h0, h1), pkh(h2, h3));
    *(uint2*)(g_x_lo + row * FEAT + c4 * 4) = make_uint2(pkh(e0, e1), pkh(e2, e3));
}

// ---------------- main GEMM + periodic epilogue ----------------
__global__ __launch_bounds__(NTHREADS, 1)
void t2v_gemm(const float* __restrict__ P,
              const float* __restrict__ swq,
              const float* __restrict__ cwq,
              float* __restrict__ out) {
    extern __shared__ char smem[];
    const uint32_t sb = smem_u32(smem);
    const int tid = threadIdx.x;
    const int wid = tid >> 5;
    const int l   = tid & 31;
    const int wm  = wid >> 1;          // 0..3  (M direction, 32 rows each)
    const int wn  = wid & 1;           // 0..1  (N direction, 64 cols each)

    const int nT = blockIdx.x;         // N fastest -> A rows shared in L2
    const int mT = blockIdx.y;
    const int m0 = mT * MT;
    const int n0 = nT * NT;

    // ldmatrix per-lane address components (verified in R4)
    const uint32_t aBase = (uint32_t)(wm * 32 + (l & 15)) * 128;
    const uint32_t kA    = (uint32_t)(l >> 4) * 16;
    const uint32_t bBase = (uint32_t)(wn * 64 + ((l >> 4) << 3) + (l & 7)) * 128;
    const uint32_t kB    = (uint32_t)((l >> 3) & 1) * 16;
    const uint32_t lx    = (uint32_t)(l & 7) << 4;

    float acc[2][8][4];
#pragma unroll
    for (int a = 0; a < 2; ++a)
#pragma unroll
        for (int b = 0; b < 8; ++b)
#pragma unroll
            for (int c = 0; c < 4; ++c) acc[a][b][c] = 0.f;

#define PREFETCH(kc, st) do { const int kb = (kc) * KC; \
    _Pragma("unroll") \
    for (int i = 0; i < 4; ++i) { \
        const int row = (i * NTHREADS + tid) >> 3; \
        const int ch  = tid & 7; \
        const uint32_t off = SWZ((uint32_t)(row * 128 + ch * 16)); \
        const size_t ga = (size_t)(m0 + row) * FEAT + kb + ch * 8; \
        const size_t gb = (size_t)(n0 + row) * FEAT + kb + ch * 8; \
        CP16(sb + (st) + off,               g_x_hi + ga); \
        CP16(sb + (st) + AB + off,          g_x_lo + ga); \
        CP16(sb + (st) + 2*AB + off,        g_Wt_hi + gb); \
        CP16(sb + (st) + 2*AB + BB + off,   g_Wt_lo + gb); \
    } } while (0)

#define COMPUTE(st) do { \
    _Pragma("unroll") \
    for (int ks = 0; ks < 4; ++ks) { \
        uint32_t ah[2][4], ae[2][4], bh[8][2], be[8][2]; \
        const uint32_t ka  = ((uint32_t)(ks * 32) + kA) ^ lx; \
        const uint32_t kbb = ((uint32_t)(ks * 32) + kB) ^ lx; \
        _Pragma("unroll") \
        for (int mt = 0; mt < 2; ++mt) { \
            const uint32_t ad = sb + (st) + aBase + mt * 2048 + ka; \
            LDSM4(ah[mt][0], ah[mt][1], ah[mt][2], ah[mt][3], ad); \
            LDSM4(ae[mt][0], ae[mt][1], ae[mt][2], ae[mt][3], ad + AB); \
        } \
        _Pragma("unroll") \
        for (int g4 = 0; g4 < 4; ++g4) { \
            const uint32_t bd = sb + (st) + 2 * AB + bBase + g4 * 2048 + kbb; \
            LDSM4(bh[2*g4][0], bh[2*g4][1], bh[2*g4+1][0], bh[2*g4+1][1], bd); \
            LDSM4(be[2*g4][0], be[2*g4][1], be[2*g4+1][0], be[2*g4+1][1], bd + BB); \
        } \
        _Pragma("unroll") \
        for (int mt = 0; mt < 2; ++mt) \
            _Pragma("unroll") \
            for (int nn = 0; nn < 8; ++nn) \
                MMA16816(acc[mt][nn], ah[mt], bh[nn]); \
        _Pragma("unroll") \
        for (int mt = 0; mt < 2; ++mt) \
            _Pragma("unroll") \
            for (int nn = 0; nn < 8; ++nn) \
                MMA16816(acc[mt][nn], ah[mt], be[nn]); \
        _Pragma("unroll") \
        for (int mt = 0; mt < 2; ++mt) \
            _Pragma("unroll") \
            for (int nn = 0; nn < 8; ++nn) \
                MMA16816(acc[mt][nn], ae[mt], bh[nn]); \
    } } while (0)

    // ---- prologue: stages 0 and 1 in flight ----
    PREFETCH(0, 0u);
    CPCOMMIT();
    PREFETCH(1, STAGE);
    CPCOMMIT();

    // ---- 3-stage pipelined mainloop; wait_group<1>, never a full drain ----
    const uint32_t stq[NSTAGES] = {0u, STAGE, 2u * STAGE};
    for (int kc = 0; kc < KITERS; ++kc) {
        CPWAIT1();              // group kc complete (only kc+1 [+empty] pending)
        __syncthreads();        // all warps done reading stage (kc+2)%3 (= kc-1)
        if (kc + 2 < KITERS) {
            PREFETCH(kc + 2, stq[(kc + 2) % NSTAGES]);
        }
        CPCOMMIT();             // commit (possibly empty) keeps counting uniform
        COMPUTE(stq[kc % NSTAGES]);
    }

    // ---- epilogue: z + P -> sine_w*sin + cosine_w*cos ----
    const float s_w = swq[0], c_w = cwq[0];
#pragma unroll
    for (int mt = 0; mt < 2; ++mt) {
        const int r0 = m0 + wm * 32 + mt * 16 + (l >> 2);
#pragma unroll
        for (int nn = 0; nn < 8; ++nn) {
            const int c = n0 + wn * 64 + nn * 8 + (l & 3) * 2;
            const float p0 = __ldg(P + c);
            const float p1 = __ldg(P + c + 1);
            float2 o0, o1;
            o0.x = t2v_periodic(acc[mt][nn][0] + p0, s_w, c_w);
            o0.y = t2v_periodic(acc[mt][nn][1] + p1, s_w, c_w);
            o1.x = t2v_periodic(acc[mt][nn][2] + p0, s_w, c_w);
            o1.y = t2v_periodic(acc[mt][nn][3] + p1, s_w, c_w);
            *(float2*)(out + (size_t)r0 * OUTW + FEAT + c) = o0;
            *(float2*)(out + (size_t)(r0 + 8) * OUTW + FEAT + c) = o1;
        }
    }
}

// ---------------- launch ----------------
extern "C" void kernel_launch(void* const* d_in, const int* in_sizes, int n_in,
                              void* d_out, int out_size) {
    (void)in_sizes; (void)n_in; (void)out_size;
    const float* x  = (const float*)d_in[0];
    const float* W  = (const float*)d_in[1];
    const float* P  = (const float*)d_in[2];
    const float* w  = (const float*)d_in[3];
    const float* p  = (const float*)d_in[4];
    const float* sw = (const float*)d_in[5];
    const float* cw = (const float*)d_in[6];
    float* out = (float*)d_out;

    cudaFuncSetAttribute(t2v_gemm, cudaFuncAttributeMaxDynamicSharedMemorySize, SMEM_TOTAL);

    t2v_cvtW<<<dim3(FEAT / 32, FEAT / 32), dim3(32, 32)>>>(W);
    t2v_cvtX<<<(B_ROWS * (FEAT / 4)) / 256, 256>>>(x, w, p, out);
    t2v_gemm<<<dim3(FEAT / NT, B_ROWS / MT), NTHREADS, SMEM_TOTAL>>>(P, sw, cw, out);
}